// round 3
// baseline (speedup 1.0000x reference)
#include <cuda_runtime.h>
#include <math.h>

// ---------------- problem constants ----------------
#define NN 10000
#define DD 256
#define EE 320000
#define MAXNORM 0.996f          // (1 - 4e-3)/sqrt(c), c=1
#define MINNORM 1e-15f
#define ATANH_CLIP (1.0f - 1e-7f)

// ---------------- scratch (static device globals; no allocation) ----------
__device__ float g_h  [NN * DD];
__device__ float g_mx [NN * DD];
__device__ float g_xt [NN * DD];
__device__ float g_bias[DD];
__device__ float g_biasy2;
// CSR-by-dst
__device__ int   g_cnt[NN];
__device__ int   g_off[NN + 1];
__device__ int   g_pos[NN];
__device__ int   g_csr_src[EE];
__device__ float g_csr_w[EE];

// ---------------- numerics (flag-independent accurate tanh/atanh) ---------
__device__ __forceinline__ float tanh_acc(float x) {
    float a = fabsf(x);
    if (a > 15.f) return copysignf(1.f, x);
    float s = expm1f(2.f * a);
    float r = s / (s + 2.f);
    return copysignf(r, x);
}
__device__ __forceinline__ float atanh_clip(float r) {
    float a = fminf(r, ATANH_CLIP);
    return 0.5f * log1pf(2.f * a / (1.f - a));
}

// ---------------- small float4 helpers ----------------
__device__ __forceinline__ float d4(float4 v)  { return v.x*v.x + v.y*v.y + v.z*v.z + v.w*v.w; }
__device__ __forceinline__ float dd4(float4 a, float4 b) { return a.x*b.x + a.y*b.y + a.z*b.z + a.w*b.w; }
__device__ __forceinline__ float4 s4(float4 v, float s) { return make_float4(v.x*s, v.y*s, v.z*s, v.w*s); }
__device__ __forceinline__ void fma4(float4& a, float4 v, float w) {
    a.x = fmaf(v.x, w, a.x); a.y = fmaf(v.y, w, a.y);
    a.z = fmaf(v.z, w, a.z); a.w = fmaf(v.w, w, a.w);
}

__device__ __forceinline__ float wredsum(float v) {
    #pragma unroll
    for (int o = 16; o; o >>= 1) v += __shfl_xor_sync(0xffffffffu, v, o);
    return v;
}
__device__ __forceinline__ float rownorm(float4 a0, float4 a1) {
    return fmaxf(sqrtf(wredsum(d4(a0) + d4(a1))), MINNORM);
}

// ---------------- stage A: h = proj(expmap0(x)) ----------------
__global__ void k_init(const float* __restrict__ x) {
    int w = threadIdx.x >> 5, lane = threadIdx.x & 31;
    int row = blockIdx.x * 8 + w;
    if (row >= NN) return;
    const float4* xp = (const float4*)x + (size_t)row * 64;
    float4 v0 = xp[lane], v1 = xp[lane + 32];
    float n = rownorm(v0, v1);
    float s = tanh_acc(n) / n;
    float4 e0 = s4(v0, s), e1 = s4(v1, s);
    float n2 = rownorm(e0, e1);
    if (n2 > MAXNORM) { float f = MAXNORM / n2; e0 = s4(e0, f); e1 = s4(e1, f); }
    float4* hp = (float4*)g_h + (size_t)row * 64;
    hp[lane] = e0; hp[lane + 32] = e1;
}

// ---------------- CSR build ----------------
__global__ void k_zerocnt() {
    int i = blockIdx.x * blockDim.x + threadIdx.x;
    if (i < NN) g_cnt[i] = 0;
}
__global__ void k_hist(const int* __restrict__ edst) {
    int i = blockIdx.x * blockDim.x + threadIdx.x;
    if (i < EE) atomicAdd(&g_cnt[edst[i]], 1);
}
__global__ __launch_bounds__(1024) void k_scan() {
    __shared__ int warp_sums[32];
    __shared__ int carry_s;
    int lane = threadIdx.x & 31, wid = threadIdx.x >> 5;
    if (threadIdx.x == 0) carry_s = 0;
    __syncthreads();
    for (int base = 0; base < NN; base += 1024) {
        int i = base + threadIdx.x;
        int v = (i < NN) ? g_cnt[i] : 0;
        int x = v;
        #pragma unroll
        for (int o = 1; o < 32; o <<= 1) {
            int y = __shfl_up_sync(0xffffffffu, x, o);
            if (lane >= o) x += y;
        }
        if (lane == 31) warp_sums[wid] = x;
        __syncthreads();
        if (wid == 0) {
            int s = warp_sums[lane];
            #pragma unroll
            for (int o = 1; o < 32; o <<= 1) {
                int y = __shfl_up_sync(0xffffffffu, s, o);
                if (lane >= o) s += y;
            }
            warp_sums[lane] = s;
        }
        __syncthreads();
        int warp_prefix = (wid == 0) ? 0 : warp_sums[wid - 1];
        int carry = carry_s;
        int excl = carry + warp_prefix + x - v;
        if (i < NN) { g_off[i] = excl; g_pos[i] = excl; }
        int total = warp_sums[31];
        __syncthreads();
        if (threadIdx.x == 0) carry_s = carry + total;
        __syncthreads();
    }
    if (threadIdx.x == 0) g_off[NN] = carry_s;
}
__global__ void k_fill(const int* __restrict__ esrc, const int* __restrict__ edst,
                       const float* __restrict__ ew) {
    int i = blockIdx.x * blockDim.x + threadIdx.x;
    if (i < EE) {
        int d = edst[i];
        int p = atomicAdd(&g_pos[d], 1);
        g_csr_src[p] = esrc[i];
        g_csr_w[p]   = ew[i];
    }
}

// ---------------- bias: hyp_bias = proj(expmap0(b)), plus |bias|^2 --------
__global__ void k_bias(const float* __restrict__ b) {
    int lane = threadIdx.x;   // 32 threads, 1 warp
    const float4* bp = (const float4*)b;
    float4 v0 = bp[lane], v1 = bp[lane + 32];
    float n = rownorm(v0, v1);
    float s = tanh_acc(n) / n;
    v0 = s4(v0, s); v1 = s4(v1, s);
    float n2 = rownorm(v0, v1);
    if (n2 > MAXNORM) { float f = MAXNORM / n2; v0 = s4(v0, f); v1 = s4(v1, f); }
    float y2 = wredsum(d4(v0) + d4(v1));
    ((float4*)g_bias)[lane] = v0;
    ((float4*)g_bias)[lane + 32] = v1;
    if (lane == 0) g_biasy2 = y2;
}

// ---------------- GEMM: g_mx = g_h @ W^T  (M=NN, N=K=256) ----------------
__global__ __launch_bounds__(256) void k_gemm(const float* __restrict__ Bm) {
    __shared__ float As[32][64];
    __shared__ float Bs[32][64];
    int tid = threadIdx.x;
    int tx = tid & 15, ty = tid >> 4;
    int m0 = blockIdx.y * 64;
    int n0 = blockIdx.x * 64;
    float acc[4][4];
    #pragma unroll
    for (int i = 0; i < 4; i++)
        #pragma unroll
        for (int j = 0; j < 4; j++) acc[i][j] = 0.f;

    for (int k0 = 0; k0 < 256; k0 += 32) {
        #pragma unroll
        for (int l = 0; l < 2; l++) {
            int idx = tid + 256 * l;
            int r = idx >> 3, c4 = idx & 7;
            float4 a = make_float4(0.f, 0.f, 0.f, 0.f);
            if (m0 + r < NN)
                a = *(const float4*)(g_h + (size_t)(m0 + r) * 256 + k0 + c4 * 4);
            As[c4*4+0][r] = a.x; As[c4*4+1][r] = a.y; As[c4*4+2][r] = a.z; As[c4*4+3][r] = a.w;
            float4 b = *(const float4*)(Bm + (size_t)(n0 + r) * 256 + k0 + c4 * 4);
            Bs[c4*4+0][r] = b.x; Bs[c4*4+1][r] = b.y; Bs[c4*4+2][r] = b.z; Bs[c4*4+3][r] = b.w;
        }
        __syncthreads();
        #pragma unroll
        for (int kk = 0; kk < 32; kk++) {
            float4 av = *(const float4*)&As[kk][ty * 4];
            float4 bv = *(const float4*)&Bs[kk][tx * 4];
            float ar[4] = {av.x, av.y, av.z, av.w};
            float br[4] = {bv.x, bv.y, bv.z, bv.w};
            #pragma unroll
            for (int i = 0; i < 4; i++)
                #pragma unroll
                for (int j = 0; j < 4; j++) acc[i][j] += ar[i] * br[j];
        }
        __syncthreads();
    }
    #pragma unroll
    for (int i = 0; i < 4; i++) {
        int m = m0 + ty * 4 + i;
        if (m < NN) {
            float4 v = make_float4(acc[i][0], acc[i][1], acc[i][2], acc[i][3]);
            *(float4*)(g_mx + (size_t)m * 256 + n0 + tx * 4) = v;
        }
    }
}

// ---------------- fused HypLinear tail + logmap0 → g_xt ----------------
__global__ void k_pre() {
    int w = threadIdx.x >> 5, lane = threadIdx.x & 31;
    int row = blockIdx.x * 8 + w;
    if (row >= NN) return;
    const float4* hp = (const float4*)g_h  + (size_t)row * 64;
    const float4* mp = (const float4*)g_mx + (size_t)row * 64;
    float4 h0 = hp[lane], h1 = hp[lane + 32];
    float4 m0 = mp[lane], m1 = mp[lane + 32];

    // mobius_matvec
    float xn  = rownorm(h0, h1);
    float mn2 = wredsum(d4(m0) + d4(m1));
    bool  zero = (mn2 == 0.f);
    float mxn = fmaxf(sqrtf(mn2), MINNORM);
    float arg = mxn / xn * atanh_clip(xn);
    float sc  = tanh_acc(arg) / mxn;
    if (zero) sc = 0.f;
    float4 r0 = s4(m0, sc), r1 = s4(m1, sc);
    float rn = rownorm(r0, r1);
    if (rn > MAXNORM) { float f = MAXNORM / rn; r0 = s4(r0, f); r1 = s4(r1, f); }

    // mobius_add with hyp_bias
    float4 b0 = ((const float4*)g_bias)[lane];
    float4 b1 = ((const float4*)g_bias)[lane + 32];
    float x2 = wredsum(d4(r0) + d4(r1));
    float xy = wredsum(dd4(r0, b0) + dd4(r1, b1));
    float y2 = g_biasy2;
    float ca = 1.f + 2.f * xy + y2;
    float cb = 1.f - x2;
    float den = fmaxf(1.f + 2.f * xy + x2 * y2, MINNORM);
    float4 q0, q1;
    q0.x = (ca*r0.x + cb*b0.x)/den; q0.y = (ca*r0.y + cb*b0.y)/den;
    q0.z = (ca*r0.z + cb*b0.z)/den; q0.w = (ca*r0.w + cb*b0.w)/den;
    q1.x = (ca*r1.x + cb*b1.x)/den; q1.y = (ca*r1.y + cb*b1.y)/den;
    q1.z = (ca*r1.z + cb*b1.z)/den; q1.w = (ca*r1.w + cb*b1.w)/den;
    float qn = rownorm(q0, q1);
    if (qn > MAXNORM) { float f = MAXNORM / qn; q0 = s4(q0, f); q1 = s4(q1, f); }

    // logmap0
    float pn = rownorm(q0, q1);
    float ls = atanh_clip(pn) / pn;
    q0 = s4(q0, ls); q1 = s4(q1, ls);

    float4* xp = (float4*)g_xt + (size_t)row * 64;
    xp[lane] = q0; xp[lane + 32] = q1;
}

// ---------------- fused CSR aggregation + HypAgg/HypAct tail -------------
// agg = sum_e w_e * xt[src_e]  (register-resident), then
// h = proj(expmap0( relu(logmap0( proj(expmap0(agg)) )) ))
__global__ __launch_bounds__(256) void k_aggpost(float* __restrict__ out, int write_out) {
    int w = threadIdx.x >> 5, lane = threadIdx.x & 31;
    int row = blockIdx.x * 8 + w;
    if (row >= NN) return;
    int beg = g_off[row], end = g_off[row + 1];

    float4 a0 = make_float4(0.f, 0.f, 0.f, 0.f);
    float4 a1 = make_float4(0.f, 0.f, 0.f, 0.f);
    int e = beg;
    for (; e + 1 < end; e += 2) {
        int   s0 = __ldg(&g_csr_src[e]);
        int   s1 = __ldg(&g_csr_src[e + 1]);
        float w0 = __ldg(&g_csr_w[e]);
        float w1 = __ldg(&g_csr_w[e + 1]);
        const float4* p0 = (const float4*)g_xt + (size_t)s0 * 64;
        const float4* p1 = (const float4*)g_xt + (size_t)s1 * 64;
        float4 u0 = __ldg(&p0[lane]);
        float4 u1 = __ldg(&p0[lane + 32]);
        float4 v0 = __ldg(&p1[lane]);
        float4 v1 = __ldg(&p1[lane + 32]);
        fma4(a0, u0, w0); fma4(a1, u1, w0);
        fma4(a0, v0, w1); fma4(a1, v1, w1);
    }
    if (e < end) {
        int   s0 = __ldg(&g_csr_src[e]);
        float w0 = __ldg(&g_csr_w[e]);
        const float4* p0 = (const float4*)g_xt + (size_t)s0 * 64;
        float4 u0 = __ldg(&p0[lane]);
        float4 u1 = __ldg(&p0[lane + 32]);
        fma4(a0, u0, w0); fma4(a1, u1, w0);
    }

    // expmap0
    float n1 = rownorm(a0, a1);
    float s = tanh_acc(n1) / n1;
    float4 e0 = s4(a0, s), e1 = s4(a1, s);
    // proj
    float n2 = rownorm(e0, e1);
    if (n2 > MAXNORM) { float f = MAXNORM / n2; e0 = s4(e0, f); e1 = s4(e1, f); }
    // logmap0 + relu
    float pn = rownorm(e0, e1);
    float ls = atanh_clip(pn) / pn;
    float4 u0, u1;
    u0.x = fmaxf(e0.x * ls, 0.f); u0.y = fmaxf(e0.y * ls, 0.f);
    u0.z = fmaxf(e0.z * ls, 0.f); u0.w = fmaxf(e0.w * ls, 0.f);
    u1.x = fmaxf(e1.x * ls, 0.f); u1.y = fmaxf(e1.y * ls, 0.f);
    u1.z = fmaxf(e1.z * ls, 0.f); u1.w = fmaxf(e1.w * ls, 0.f);
    // expmap0
    float un = rownorm(u0, u1);
    float s2 = tanh_acc(un) / un;
    float4 o0 = s4(u0, s2), o1 = s4(u1, s2);
    // proj
    float n3 = rownorm(o0, o1);
    if (n3 > MAXNORM) { float f = MAXNORM / n3; o0 = s4(o0, f); o1 = s4(o1, f); }

    float4* dst = write_out ? ((float4*)out + (size_t)row * 64)
                            : ((float4*)g_h + (size_t)row * 64);
    dst[lane] = o0; dst[lane + 32] = o1;
}

// ---------------- launch ----------------
extern "C" void kernel_launch(void* const* d_in, const int* in_sizes, int n_in,
                              void* d_out, int out_size) {
    const float* x    = (const float*)d_in[0];
    const float* W1   = (const float*)d_in[1];
    const float* b1   = (const float*)d_in[2];
    const float* W2   = (const float*)d_in[3];
    const float* b2   = (const float*)d_in[4];
    const float* ew   = (const float*)d_in[5];
    const int*   esrc = (const int*)d_in[6];
    const int*   edst = (const int*)d_in[7];
    float* out = (float*)d_out;
    (void)in_sizes; (void)n_in; (void)out_size;

    const int rowBlocks = (NN + 7) / 8;
    dim3 gemmGrid(256 / 64, (NN + 63) / 64);
    const int eBlocks = (EE + 255) / 256;

    k_init<<<rowBlocks, 256>>>(x);

    // CSR build (once; reused by both layers)
    k_zerocnt<<<(NN + 255) / 256, 256>>>();
    k_hist<<<eBlocks, 256>>>(edst);
    k_scan<<<1, 1024>>>();
    k_fill<<<eBlocks, 256>>>(esrc, edst, ew);

    // layer 1
    k_gemm<<<gemmGrid, 256>>>(W1);
    k_bias<<<1, 32>>>(b1);
    k_pre<<<rowBlocks, 256>>>();
    k_aggpost<<<rowBlocks, 256>>>(out, 0);

    // layer 2
    k_gemm<<<gemmGrid, 256>>>(W2);
    k_bias<<<1, 32>>>(b2);
    k_pre<<<rowBlocks, 256>>>();
    k_aggpost<<<rowBlocks, 256>>>(out, 1);
}

// round 5
// speedup vs baseline: 1.4803x; 1.4803x over previous
#include <cuda_runtime.h>
#include <math.h>

// ---------------- problem constants ----------------
#define NN 10000
#define DD 256
#define EE 320000
#define MAXNORM 0.996f          // (1 - 4e-3)/sqrt(c), c=1
#define MINNORM 1e-15f
#define ATANH_CLIP (1.0f - 1e-7f)

// ---------------- scratch (static device globals; no allocation) ----------
__device__ float g_h  [NN * DD];
__device__ float g_mx [NN * DD];
__device__ float g_xt [NN * DD];
__device__ float g_bias[DD];
__device__ float g_biasy2;
// CSR-by-dst
__device__ int   g_cnt[NN];
__device__ int   g_off[NN + 1];
__device__ int   g_pos[NN];
__device__ int   g_csr_src[EE];
__device__ float g_csr_w[EE];

// ---------------- numerics (flag-independent accurate tanh/atanh) ---------
__device__ __forceinline__ float tanh_acc(float x) {
    float a = fabsf(x);
    if (a > 15.f) return copysignf(1.f, x);
    float s = expm1f(2.f * a);
    float r = s / (s + 2.f);
    return copysignf(r, x);
}
__device__ __forceinline__ float atanh_clip(float r) {
    float a = fminf(r, ATANH_CLIP);
    return 0.5f * log1pf(2.f * a / (1.f - a));
}

// ---------------- small float4 helpers ----------------
__device__ __forceinline__ float d4(float4 v)  { return v.x*v.x + v.y*v.y + v.z*v.z + v.w*v.w; }
__device__ __forceinline__ float dd4(float4 a, float4 b) { return a.x*b.x + a.y*b.y + a.z*b.z + a.w*b.w; }
__device__ __forceinline__ float4 s4(float4 v, float s) { return make_float4(v.x*s, v.y*s, v.z*s, v.w*s); }
__device__ __forceinline__ void fma4(float4& a, float4 v, float w) {
    a.x = fmaf(v.x, w, a.x); a.y = fmaf(v.y, w, a.y);
    a.z = fmaf(v.z, w, a.z); a.w = fmaf(v.w, w, a.w);
}

__device__ __forceinline__ float wredsum(float v) {
    #pragma unroll
    for (int o = 16; o; o >>= 1) v += __shfl_xor_sync(0xffffffffu, v, o);
    return v;
}
__device__ __forceinline__ float rownorm(float4 a0, float4 a1) {
    return fmaxf(sqrtf(wredsum(d4(a0) + d4(a1))), MINNORM);
}

// ---------------- stage A: h = proj(expmap0(x)); also zero g_cnt ---------
__global__ void k_init(const float* __restrict__ x) {
    int gi = blockIdx.x * blockDim.x + threadIdx.x;
    if (gi < NN) g_cnt[gi] = 0;
    int w = threadIdx.x >> 5, lane = threadIdx.x & 31;
    int row = blockIdx.x * 8 + w;
    if (row >= NN) return;
    const float4* xp = (const float4*)x + (size_t)row * 64;
    float4 v0 = xp[lane], v1 = xp[lane + 32];
    float n = rownorm(v0, v1);
    float s = tanh_acc(n) / n;
    float4 e0 = s4(v0, s), e1 = s4(v1, s);
    float n2 = rownorm(e0, e1);
    if (n2 > MAXNORM) { float f = MAXNORM / n2; e0 = s4(e0, f); e1 = s4(e1, f); }
    float4* hp = (float4*)g_h + (size_t)row * 64;
    hp[lane] = e0; hp[lane + 32] = e1;
}

// ---------------- CSR build ----------------
__global__ void k_hist(const int* __restrict__ edst) {
    int i = blockIdx.x * blockDim.x + threadIdx.x;
    if (i < EE) atomicAdd(&g_cnt[edst[i]], 1);
}

// single block, each thread owns 10 consecutive counters; 2 barriers total
__global__ __launch_bounds__(1024) void k_scan() {
    __shared__ int warp_sums[32];
    int tid = threadIdx.x, lane = tid & 31, wid = tid >> 5;
    int base = tid * 10;
    int v[10]; int s = 0;
    #pragma unroll
    for (int j = 0; j < 10; j++) {
        int i = base + j;
        v[j] = (i < NN) ? g_cnt[i] : 0;
        s += v[j];
    }
    int x = s;
    #pragma unroll
    for (int o = 1; o < 32; o <<= 1) {
        int y = __shfl_up_sync(0xffffffffu, x, o);
        if (lane >= o) x += y;
    }
    if (lane == 31) warp_sums[wid] = x;
    __syncthreads();
    if (wid == 0) {
        int t = warp_sums[lane];
        #pragma unroll
        for (int o = 1; o < 32; o <<= 1) {
            int y = __shfl_up_sync(0xffffffffu, t, o);
            if (lane >= o) t += y;
        }
        warp_sums[lane] = t;
    }
    __syncthreads();
    int prefix = ((wid > 0) ? warp_sums[wid - 1] : 0) + (x - s);  // exclusive
    #pragma unroll
    for (int j = 0; j < 10; j++) {
        int i = base + j;
        if (i < NN) { g_off[i] = prefix; g_pos[i] = prefix; }
        prefix += v[j];
    }
    if (tid == 1023) g_off[NN] = prefix;   // thread 1023's range is past NN -> prefix == total
}

__global__ void k_fill(const int* __restrict__ esrc, const int* __restrict__ edst,
                       const float* __restrict__ ew) {
    int i = blockIdx.x * blockDim.x + threadIdx.x;
    if (i < EE) {
        int d = edst[i];
        int p = atomicAdd(&g_pos[d], 1);
        g_csr_src[p] = esrc[i];
        g_csr_w[p]   = ew[i];
    }
}

// ---------------- bias: hyp_bias = proj(expmap0(b)), plus |bias|^2 --------
__global__ void k_bias(const float* __restrict__ b) {
    int lane = threadIdx.x;   // 32 threads, 1 warp
    const float4* bp = (const float4*)b;
    float4 v0 = bp[lane], v1 = bp[lane + 32];
    float n = rownorm(v0, v1);
    float s = tanh_acc(n) / n;
    v0 = s4(v0, s); v1 = s4(v1, s);
    float n2 = rownorm(v0, v1);
    if (n2 > MAXNORM) { float f = MAXNORM / n2; v0 = s4(v0, f); v1 = s4(v1, f); }
    float y2 = wredsum(d4(v0) + d4(v1));
    ((float4*)g_bias)[lane] = v0;
    ((float4*)g_bias)[lane + 32] = v1;
    if (lane == 0) g_biasy2 = y2;
}

// ---------------- GEMM: g_mx = g_h @ W^T  (M=NN, N=K=256) ----------------
__global__ __launch_bounds__(256) void k_gemm(const float* __restrict__ Bm) {
    __shared__ float As[32][64];
    __shared__ float Bs[32][64];
    int tid = threadIdx.x;
    int tx = tid & 15, ty = tid >> 4;
    int m0 = blockIdx.y * 64;
    int n0 = blockIdx.x * 64;
    float acc[4][4];
    #pragma unroll
    for (int i = 0; i < 4; i++)
        #pragma unroll
        for (int j = 0; j < 4; j++) acc[i][j] = 0.f;

    for (int k0 = 0; k0 < 256; k0 += 32) {
        #pragma unroll
        for (int l = 0; l < 2; l++) {
            int idx = tid + 256 * l;
            int r = idx >> 3, c4 = idx & 7;
            float4 a = make_float4(0.f, 0.f, 0.f, 0.f);
            if (m0 + r < NN)
                a = *(const float4*)(g_h + (size_t)(m0 + r) * 256 + k0 + c4 * 4);
            As[c4*4+0][r] = a.x; As[c4*4+1][r] = a.y; As[c4*4+2][r] = a.z; As[c4*4+3][r] = a.w;
            float4 b = *(const float4*)(Bm + (size_t)(n0 + r) * 256 + k0 + c4 * 4);
            Bs[c4*4+0][r] = b.x; Bs[c4*4+1][r] = b.y; Bs[c4*4+2][r] = b.z; Bs[c4*4+3][r] = b.w;
        }
        __syncthreads();
        #pragma unroll
        for (int kk = 0; kk < 32; kk++) {
            float4 av = *(const float4*)&As[kk][ty * 4];
            float4 bv = *(const float4*)&Bs[kk][tx * 4];
            float ar[4] = {av.x, av.y, av.z, av.w};
            float br[4] = {bv.x, bv.y, bv.z, bv.w};
            #pragma unroll
            for (int i = 0; i < 4; i++)
                #pragma unroll
                for (int j = 0; j < 4; j++) acc[i][j] += ar[i] * br[j];
        }
        __syncthreads();
    }
    #pragma unroll
    for (int i = 0; i < 4; i++) {
        int m = m0 + ty * 4 + i;
        if (m < NN) {
            float4 v = make_float4(acc[i][0], acc[i][1], acc[i][2], acc[i][3]);
            *(float4*)(g_mx + (size_t)m * 256 + n0 + tx * 4) = v;
        }
    }
}

// ---------------- fused HypLinear tail + logmap0 → g_xt ----------------
__global__ void k_pre() {
    int w = threadIdx.x >> 5, lane = threadIdx.x & 31;
    int row = blockIdx.x * 8 + w;
    if (row >= NN) return;
    const float4* hp = (const float4*)g_h  + (size_t)row * 64;
    const float4* mp = (const float4*)g_mx + (size_t)row * 64;
    float4 h0 = hp[lane], h1 = hp[lane + 32];
    float4 m0 = mp[lane], m1 = mp[lane + 32];

    // mobius_matvec
    float xn  = rownorm(h0, h1);
    float mn2 = wredsum(d4(m0) + d4(m1));
    bool  zero = (mn2 == 0.f);
    float mxn = fmaxf(sqrtf(mn2), MINNORM);
    float arg = mxn / xn * atanh_clip(xn);
    float sc  = tanh_acc(arg) / mxn;
    if (zero) sc = 0.f;
    float4 r0 = s4(m0, sc), r1 = s4(m1, sc);
    float rn = rownorm(r0, r1);
    if (rn > MAXNORM) { float f = MAXNORM / rn; r0 = s4(r0, f); r1 = s4(r1, f); }

    // mobius_add with hyp_bias
    float4 b0 = ((const float4*)g_bias)[lane];
    float4 b1 = ((const float4*)g_bias)[lane + 32];
    float x2 = wredsum(d4(r0) + d4(r1));
    float xy = wredsum(dd4(r0, b0) + dd4(r1, b1));
    float y2 = g_biasy2;
    float ca = 1.f + 2.f * xy + y2;
    float cb = 1.f - x2;
    float den = fmaxf(1.f + 2.f * xy + x2 * y2, MINNORM);
    float4 q0, q1;
    q0.x = (ca*r0.x + cb*b0.x)/den; q0.y = (ca*r0.y + cb*b0.y)/den;
    q0.z = (ca*r0.z + cb*b0.z)/den; q0.w = (ca*r0.w + cb*b0.w)/den;
    q1.x = (ca*r1.x + cb*b1.x)/den; q1.y = (ca*r1.y + cb*b1.y)/den;
    q1.z = (ca*r1.z + cb*b1.z)/den; q1.w = (ca*r1.w + cb*b1.w)/den;
    float qn = rownorm(q0, q1);
    if (qn > MAXNORM) { float f = MAXNORM / qn; q0 = s4(q0, f); q1 = s4(q1, f); }

    // logmap0
    float pn = rownorm(q0, q1);
    float ls = atanh_clip(pn) / pn;
    q0 = s4(q0, ls); q1 = s4(q1, ls);

    float4* xp = (float4*)g_xt + (size_t)row * 64;
    xp[lane] = q0; xp[lane + 32] = q1;
}

// ---------------- fused CSR aggregation + HypAgg/HypAct tail -------------
// warp per dst row; edge (src,w) pairs loaded 32-at-a-time into registers,
// broadcast via shfl (no index-load dependency chain in the inner loop)
__global__ __launch_bounds__(256) void k_aggpost(float* __restrict__ out, int write_out) {
    int w = threadIdx.x >> 5, lane = threadIdx.x & 31;
    int row = blockIdx.x * 8 + w;
    if (row >= NN) return;
    int beg = g_off[row], end = g_off[row + 1];

    float4 a0 = make_float4(0.f, 0.f, 0.f, 0.f);
    float4 a1 = make_float4(0.f, 0.f, 0.f, 0.f);

    for (int c = beg; c < end; c += 32) {
        int n = end - c; if (n > 32) n = 32;
        int   sv = 0; float wv = 0.f;
        if (lane < n) {
            sv = __ldg(&g_csr_src[c + lane]);
            wv = __ldg(&g_csr_w[c + lane]);
        }
        int j = 0;
        for (; j + 1 < n; j += 2) {
            int   s0 = __shfl_sync(0xffffffffu, sv, j);
            int   s1 = __shfl_sync(0xffffffffu, sv, j + 1);
            float w0 = __shfl_sync(0xffffffffu, wv, j);
            float w1 = __shfl_sync(0xffffffffu, wv, j + 1);
            const float4* p0 = (const float4*)g_xt + (size_t)s0 * 64;
            const float4* p1 = (const float4*)g_xt + (size_t)s1 * 64;
            float4 u0 = __ldg(&p0[lane]);
            float4 u1 = __ldg(&p0[lane + 32]);
            float4 t0 = __ldg(&p1[lane]);
            float4 t1 = __ldg(&p1[lane + 32]);
            fma4(a0, u0, w0); fma4(a1, u1, w0);
            fma4(a0, t0, w1); fma4(a1, t1, w1);
        }
        if (j < n) {
            int   s0 = __shfl_sync(0xffffffffu, sv, j);
            float w0 = __shfl_sync(0xffffffffu, wv, j);
            const float4* p0 = (const float4*)g_xt + (size_t)s0 * 64;
            float4 u0 = __ldg(&p0[lane]);
            float4 u1 = __ldg(&p0[lane + 32]);
            fma4(a0, u0, w0); fma4(a1, u1, w0);
        }
    }

    // expmap0
    float n1 = rownorm(a0, a1);
    float s = tanh_acc(n1) / n1;
    float4 e0 = s4(a0, s), e1 = s4(a1, s);
    // proj
    float n2 = rownorm(e0, e1);
    if (n2 > MAXNORM) { float f = MAXNORM / n2; e0 = s4(e0, f); e1 = s4(e1, f); }
    // logmap0 + relu
    float pn = rownorm(e0, e1);
    float ls = atanh_clip(pn) / pn;
    float4 u0, u1;
    u0.x = fmaxf(e0.x * ls, 0.f); u0.y = fmaxf(e0.y * ls, 0.f);
    u0.z = fmaxf(e0.z * ls, 0.f); u0.w = fmaxf(e0.w * ls, 0.f);
    u1.x = fmaxf(e1.x * ls, 0.f); u1.y = fmaxf(e1.y * ls, 0.f);
    u1.z = fmaxf(e1.z * ls, 0.f); u1.w = fmaxf(e1.w * ls, 0.f);
    // expmap0
    float un = rownorm(u0, u1);
    float s2 = tanh_acc(un) / un;
    float4 o0 = s4(u0, s2), o1 = s4(u1, s2);
    // proj
    float n3 = rownorm(o0, o1);
    if (n3 > MAXNORM) { float f = MAXNORM / n3; o0 = s4(o0, f); o1 = s4(o1, f); }

    float4* dst = write_out ? ((float4*)out + (size_t)row * 64)
                            : ((float4*)g_h + (size_t)row * 64);
    dst[lane] = o0; dst[lane + 32] = o1;
}

// ---------------- launch ----------------
extern "C" void kernel_launch(void* const* d_in, const int* in_sizes, int n_in,
                              void* d_out, int out_size) {
    const float* x    = (const float*)d_in[0];
    const float* W1   = (const float*)d_in[1];
    const float* b1   = (const float*)d_in[2];
    const float* W2   = (const float*)d_in[3];
    const float* b2   = (const float*)d_in[4];
    const float* ew   = (const float*)d_in[5];
    const int*   esrc = (const int*)d_in[6];
    const int*   edst = (const int*)d_in[7];
    float* out = (float*)d_out;
    (void)in_sizes; (void)n_in; (void)out_size;

    const int rowBlocks = (NN + 7) / 8;
    dim3 gemmGrid(256 / 64, (NN + 63) / 64);
    const int eBlocks = (EE + 255) / 256;

    k_init<<<rowBlocks, 256>>>(x);

    // CSR build (once; reused by both layers)
    k_hist<<<eBlocks, 256>>>(edst);
    k_scan<<<1, 1024>>>();
    k_fill<<<eBlocks, 256>>>(esrc, edst, ew);

    // layer 1
    k_gemm<<<gemmGrid, 256>>>(W1);
    k_bias<<<1, 32>>>(b1);
    k_pre<<<rowBlocks, 256>>>();
    k_aggpost<<<rowBlocks, 256>>>(out, 0);

    // layer 2
    k_gemm<<<gemmGrid, 256>>>(W2);
    k_bias<<<1, 32>>>(b2);
    k_pre<<<rowBlocks, 256>>>();
    k_aggpost<<<rowBlocks, 256>>>(out, 1);
}

// round 6
// speedup vs baseline: 1.5744x; 1.0636x over previous
#include <cuda_runtime.h>
#include <math.h>

// ---------------- problem constants ----------------
#define NN 10000
#define DD 256
#define EE 320000
#define MAXNORM 0.996f          // (1 - 4e-3)/sqrt(c), c=1
#define MINNORM 1e-15f
#define ATANH_CLIP (1.0f - 1e-7f)

// ---------------- scratch (static device globals; no allocation) ----------
__device__ float g_h  [NN * DD];
__device__ float g_xt [NN * DD];
__device__ float g_bias[DD];
__device__ float g_biasy2;
// CSR-by-dst
__device__ int   g_cnt[NN];
__device__ int   g_off[NN + 1];
__device__ int   g_pos[NN];
__device__ int   g_csr_src[EE];
__device__ float g_csr_w[EE];

// ---------------- numerics (flag-independent accurate tanh/atanh) ---------
__device__ __forceinline__ float tanh_acc(float x) {
    float a = fabsf(x);
    if (a > 15.f) return copysignf(1.f, x);
    float s = expm1f(2.f * a);
    float r = s / (s + 2.f);
    return copysignf(r, x);
}
__device__ __forceinline__ float atanh_clip(float r) {
    float a = fminf(r, ATANH_CLIP);
    return 0.5f * log1pf(2.f * a / (1.f - a));
}

// ---------------- small float4 helpers ----------------
__device__ __forceinline__ float d4(float4 v)  { return v.x*v.x + v.y*v.y + v.z*v.z + v.w*v.w; }
__device__ __forceinline__ float dd4(float4 a, float4 b) { return a.x*b.x + a.y*b.y + a.z*b.z + a.w*b.w; }
__device__ __forceinline__ float4 s4(float4 v, float s) { return make_float4(v.x*s, v.y*s, v.z*s, v.w*s); }
__device__ __forceinline__ void fma4(float4& a, float4 v, float w) {
    a.x = fmaf(v.x, w, a.x); a.y = fmaf(v.y, w, a.y);
    a.z = fmaf(v.z, w, a.z); a.w = fmaf(v.w, w, a.w);
}

__device__ __forceinline__ float wredsum(float v) {
    #pragma unroll
    for (int o = 16; o; o >>= 1) v += __shfl_xor_sync(0xffffffffu, v, o);
    return v;
}
__device__ __forceinline__ float rownorm(float4 a0, float4 a1) {
    return fmaxf(sqrtf(wredsum(d4(a0) + d4(a1))), MINNORM);
}

// ---------------- stage A: h = proj(expmap0(x)); also zero g_cnt ---------
__global__ void k_init(const float* __restrict__ x) {
    int gi = blockIdx.x * blockDim.x + threadIdx.x;
    if (gi < NN) g_cnt[gi] = 0;
    int w = threadIdx.x >> 5, lane = threadIdx.x & 31;
    int row = blockIdx.x * 8 + w;
    if (row >= NN) return;
    const float4* xp = (const float4*)x + (size_t)row * 64;
    float4 v0 = xp[lane], v1 = xp[lane + 32];
    float n = rownorm(v0, v1);
    float s = tanh_acc(n) / n;
    float4 e0 = s4(v0, s), e1 = s4(v1, s);
    float n2 = rownorm(e0, e1);
    if (n2 > MAXNORM) { float f = MAXNORM / n2; e0 = s4(e0, f); e1 = s4(e1, f); }
    float4* hp = (float4*)g_h + (size_t)row * 64;
    hp[lane] = e0; hp[lane + 32] = e1;
}

// ---------------- CSR build ----------------
__global__ void k_hist(const int* __restrict__ edst) {
    int i = blockIdx.x * blockDim.x + threadIdx.x;
    if (i < EE) atomicAdd(&g_cnt[edst[i]], 1);
}

// single block, each thread owns 10 consecutive counters; 2 barriers total
__global__ __launch_bounds__(1024) void k_scan() {
    __shared__ int warp_sums[32];
    int tid = threadIdx.x, lane = tid & 31, wid = tid >> 5;
    int base = tid * 10;
    int v[10]; int s = 0;
    #pragma unroll
    for (int j = 0; j < 10; j++) {
        int i = base + j;
        v[j] = (i < NN) ? g_cnt[i] : 0;
        s += v[j];
    }
    int x = s;
    #pragma unroll
    for (int o = 1; o < 32; o <<= 1) {
        int y = __shfl_up_sync(0xffffffffu, x, o);
        if (lane >= o) x += y;
    }
    if (lane == 31) warp_sums[wid] = x;
    __syncthreads();
    if (wid == 0) {
        int t = warp_sums[lane];
        #pragma unroll
        for (int o = 1; o < 32; o <<= 1) {
            int y = __shfl_up_sync(0xffffffffu, t, o);
            if (lane >= o) t += y;
        }
        warp_sums[lane] = t;
    }
    __syncthreads();
    int prefix = ((wid > 0) ? warp_sums[wid - 1] : 0) + (x - s);  // exclusive
    #pragma unroll
    for (int j = 0; j < 10; j++) {
        int i = base + j;
        if (i < NN) { g_off[i] = prefix; g_pos[i] = prefix; }
        prefix += v[j];
    }
    if (tid == 1023) g_off[NN] = prefix;
}

__global__ void k_fill(const int* __restrict__ esrc, const int* __restrict__ edst,
                       const float* __restrict__ ew) {
    int i = blockIdx.x * blockDim.x + threadIdx.x;
    if (i < EE) {
        int d = edst[i];
        int p = atomicAdd(&g_pos[d], 1);
        g_csr_src[p] = esrc[i];
        g_csr_w[p]   = ew[i];
    }
}

// ---------------- bias: hyp_bias = proj(expmap0(b)), plus |bias|^2 --------
__global__ void k_bias(const float* __restrict__ b) {
    int lane = threadIdx.x;   // 32 threads, 1 warp
    const float4* bp = (const float4*)b;
    float4 v0 = bp[lane], v1 = bp[lane + 32];
    float n = rownorm(v0, v1);
    float s = tanh_acc(n) / n;
    v0 = s4(v0, s); v1 = s4(v1, s);
    float n2 = rownorm(v0, v1);
    if (n2 > MAXNORM) { float f = MAXNORM / n2; v0 = s4(v0, f); v1 = s4(v1, f); }
    float y2 = wredsum(d4(v0) + d4(v1));
    ((float4*)g_bias)[lane] = v0;
    ((float4*)g_bias)[lane + 32] = v1;
    if (lane == 0) g_biasy2 = y2;
}

// ---------------- fused GEMM + HypLinear tail + logmap0 → g_xt ------------
// tile: 40 rows x 256 cols (full width). 256 threads: ty=tid>>5 (warp, 8),
// tx=tid&31. Warp ty owns rows m0+ty*5 .. +4 completely:
// thread cols = [tx*4..tx*4+3] and [128+tx*4..128+tx*4+3].
// 10000 = 250 * 40 exactly -> no bounds checks.
#define TM 40
__global__ __launch_bounds__(256, 2) void k_gemmpre(const float* __restrict__ Wm) {
    __shared__ float As[TM][36];      // [m][k], pad 36 (144B rows, 16B aligned)
    __shared__ float Bs[32][256];     // [k][j]
    int tid = threadIdx.x;
    int tx = tid & 31, ty = tid >> 5;
    int m0 = blockIdx.x * TM;

    float4 acc0[5], acc1[5];
    #pragma unroll
    for (int r = 0; r < 5; r++) {
        acc0[r] = make_float4(0.f, 0.f, 0.f, 0.f);
        acc1[r] = make_float4(0.f, 0.f, 0.f, 0.f);
    }

    for (int k0 = 0; k0 < 256; k0 += 32) {
        // load A tile: 40x32 floats = 320 float4; threads 0..255 take idx=tid, 0..63 also idx=tid+256
        {
            int idx = tid;
            if (idx < 320) {
                int r = idx >> 3, c4 = idx & 7;
                float4 a = *(const float4*)(g_h + (size_t)(m0 + r) * 256 + k0 + c4 * 4);
                As[r][c4*4+0] = a.x; As[r][c4*4+1] = a.y; As[r][c4*4+2] = a.z; As[r][c4*4+3] = a.w;
            }
            idx = tid + 256;
            if (idx < 320) {
                int r = idx >> 3, c4 = idx & 7;
                float4 a = *(const float4*)(g_h + (size_t)(m0 + r) * 256 + k0 + c4 * 4);
                As[r][c4*4+0] = a.x; As[r][c4*4+1] = a.y; As[r][c4*4+2] = a.z; As[r][c4*4+3] = a.w;
            }
        }
        // load B tile: thread j=tid loads W[j][k0..k0+31] (8 float4), stores Bs[k][j]
        {
            const float4* wr = (const float4*)(Wm + (size_t)tid * 256 + k0);
            #pragma unroll
            for (int c4 = 0; c4 < 8; c4++) {
                float4 b = __ldg(&wr[c4]);
                Bs[c4*4+0][tid] = b.x; Bs[c4*4+1][tid] = b.y;
                Bs[c4*4+2][tid] = b.z; Bs[c4*4+3][tid] = b.w;
            }
        }
        __syncthreads();
        #pragma unroll
        for (int kk4 = 0; kk4 < 8; kk4++) {
            float4 ar[5];
            #pragma unroll
            for (int r = 0; r < 5; r++)
                ar[r] = *(const float4*)&As[ty*5 + r][kk4*4];
            #pragma unroll
            for (int q = 0; q < 4; q++) {
                float4 b0 = *(const float4*)&Bs[kk4*4+q][tx*4];
                float4 b1 = *(const float4*)&Bs[kk4*4+q][128 + tx*4];
                #pragma unroll
                for (int r = 0; r < 5; r++) {
                    float av = (q == 0) ? ar[r].x : (q == 1) ? ar[r].y : (q == 2) ? ar[r].z : ar[r].w;
                    fma4(acc0[r], b0, av);
                    fma4(acc1[r], b1, av);
                }
            }
        }
        __syncthreads();
    }

    // ---- fused epilogue: per warp, 5 complete rows ----
    float4 bb0 = ((const float4*)g_bias)[tx];
    float4 bb1 = ((const float4*)g_bias)[32 + tx];
    float y2 = g_biasy2;
    #pragma unroll
    for (int r = 0; r < 5; r++) {
        int m = m0 + ty * 5 + r;
        float4 mv0 = acc0[r], mv1 = acc1[r];

        // h row reload for xn
        const float4* hp = (const float4*)(g_h + (size_t)m * 256);
        float4 h0 = hp[tx], h1 = hp[32 + tx];
        float xn = rownorm(h0, h1);

        // mobius_matvec scaling
        float mn2 = wredsum(d4(mv0) + d4(mv1));
        bool zero = (mn2 == 0.f);
        float mxn = fmaxf(sqrtf(mn2), MINNORM);
        float arg = mxn / xn * atanh_clip(xn);
        float sc = tanh_acc(arg) / mxn;
        if (zero) sc = 0.f;
        float4 r0 = s4(mv0, sc), r1 = s4(mv1, sc);
        float rn = rownorm(r0, r1);
        if (rn > MAXNORM) { float f = MAXNORM / rn; r0 = s4(r0, f); r1 = s4(r1, f); }

        // mobius_add with hyp_bias
        float x2 = wredsum(d4(r0) + d4(r1));
        float xy = wredsum(dd4(r0, bb0) + dd4(r1, bb1));
        float ca = 1.f + 2.f * xy + y2;
        float cb = 1.f - x2;
        float den = fmaxf(1.f + 2.f * xy + x2 * y2, MINNORM);
        float4 q0, q1;
        q0.x = (ca*r0.x + cb*bb0.x)/den; q0.y = (ca*r0.y + cb*bb0.y)/den;
        q0.z = (ca*r0.z + cb*bb0.z)/den; q0.w = (ca*r0.w + cb*bb0.w)/den;
        q1.x = (ca*r1.x + cb*bb1.x)/den; q1.y = (ca*r1.y + cb*bb1.y)/den;
        q1.z = (ca*r1.z + cb*bb1.z)/den; q1.w = (ca*r1.w + cb*bb1.w)/den;
        float qn = rownorm(q0, q1);
        if (qn > MAXNORM) { float f = MAXNORM / qn; q0 = s4(q0, f); q1 = s4(q1, f); }

        // logmap0
        float pn = rownorm(q0, q1);
        float ls = atanh_clip(pn) / pn;
        q0 = s4(q0, ls); q1 = s4(q1, ls);

        float4* xp = (float4*)(g_xt + (size_t)m * 256);
        xp[tx] = q0; xp[32 + tx] = q1;
    }
}

// ---------------- fused CSR aggregation + HypAgg/HypAct tail -------------
__global__ __launch_bounds__(256) void k_aggpost(float* __restrict__ out, int write_out) {
    int w = threadIdx.x >> 5, lane = threadIdx.x & 31;
    int row = blockIdx.x * 8 + w;
    if (row >= NN) return;
    int beg = g_off[row], end = g_off[row + 1];

    float4 a0 = make_float4(0.f, 0.f, 0.f, 0.f);
    float4 a1 = make_float4(0.f, 0.f, 0.f, 0.f);

    for (int c = beg; c < end; c += 32) {
        int n = end - c; if (n > 32) n = 32;
        int   sv = 0; float wv = 0.f;
        if (lane < n) {
            sv = __ldg(&g_csr_src[c + lane]);
            wv = __ldg(&g_csr_w[c + lane]);
        }
        int j = 0;
        for (; j + 1 < n; j += 2) {
            int   s0 = __shfl_sync(0xffffffffu, sv, j);
            int   s1 = __shfl_sync(0xffffffffu, sv, j + 1);
            float w0 = __shfl_sync(0xffffffffu, wv, j);
            float w1 = __shfl_sync(0xffffffffu, wv, j + 1);
            const float4* p0 = (const float4*)g_xt + (size_t)s0 * 64;
            const float4* p1 = (const float4*)g_xt + (size_t)s1 * 64;
            float4 u0 = __ldg(&p0[lane]);
            float4 u1 = __ldg(&p0[lane + 32]);
            float4 t0 = __ldg(&p1[lane]);
            float4 t1 = __ldg(&p1[lane + 32]);
            fma4(a0, u0, w0); fma4(a1, u1, w0);
            fma4(a0, t0, w1); fma4(a1, t1, w1);
        }
        if (j < n) {
            int   s0 = __shfl_sync(0xffffffffu, sv, j);
            float w0 = __shfl_sync(0xffffffffu, wv, j);
            const float4* p0 = (const float4*)g_xt + (size_t)s0 * 64;
            float4 u0 = __ldg(&p0[lane]);
            float4 u1 = __ldg(&p0[lane + 32]);
            fma4(a0, u0, w0); fma4(a1, u1, w0);
        }
    }

    // expmap0
    float n1 = rownorm(a0, a1);
    float s = tanh_acc(n1) / n1;
    float4 e0 = s4(a0, s), e1 = s4(a1, s);
    // proj
    float n2 = rownorm(e0, e1);
    if (n2 > MAXNORM) { float f = MAXNORM / n2; e0 = s4(e0, f); e1 = s4(e1, f); }
    // logmap0 + relu
    float pn = rownorm(e0, e1);
    float ls = atanh_clip(pn) / pn;
    float4 u0, u1;
    u0.x = fmaxf(e0.x * ls, 0.f); u0.y = fmaxf(e0.y * ls, 0.f);
    u0.z = fmaxf(e0.z * ls, 0.f); u0.w = fmaxf(e0.w * ls, 0.f);
    u1.x = fmaxf(e1.x * ls, 0.f); u1.y = fmaxf(e1.y * ls, 0.f);
    u1.z = fmaxf(e1.z * ls, 0.f); u1.w = fmaxf(e1.w * ls, 0.f);
    // expmap0
    float un = rownorm(u0, u1);
    float s2 = tanh_acc(un) / un;
    float4 o0 = s4(u0, s2), o1 = s4(u1, s2);
    // proj
    float n3 = rownorm(o0, o1);
    if (n3 > MAXNORM) { float f = MAXNORM / n3; o0 = s4(o0, f); o1 = s4(o1, f); }

    float4* dst = write_out ? ((float4*)out + (size_t)row * 64)
                            : ((float4*)g_h + (size_t)row * 64);
    dst[lane] = o0; dst[lane + 32] = o1;
}

// ---------------- launch ----------------
extern "C" void kernel_launch(void* const* d_in, const int* in_sizes, int n_in,
                              void* d_out, int out_size) {
    const float* x    = (const float*)d_in[0];
    const float* W1   = (const float*)d_in[1];
    const float* b1   = (const float*)d_in[2];
    const float* W2   = (const float*)d_in[3];
    const float* b2   = (const float*)d_in[4];
    const float* ew   = (const float*)d_in[5];
    const int*   esrc = (const int*)d_in[6];
    const int*   edst = (const int*)d_in[7];
    float* out = (float*)d_out;
    (void)in_sizes; (void)n_in; (void)out_size;

    const int rowBlocks = (NN + 7) / 8;
    const int gemmBlocks = NN / TM;               // 250, exact
    const int eBlocks = (EE + 255) / 256;

    k_init<<<rowBlocks, 256>>>(x);

    // CSR build (once; reused by both layers)
    k_hist<<<eBlocks, 256>>>(edst);
    k_scan<<<1, 1024>>>();
    k_fill<<<eBlocks, 256>>>(esrc, edst, ew);

    // layer 1
    k_bias<<<1, 32>>>(b1);
    k_gemmpre<<<gemmBlocks, 256>>>(W1);
    k_aggpost<<<rowBlocks, 256>>>(out, 0);

    // layer 2
    k_bias<<<1, 32>>>(b2);
    k_gemmpre<<<gemmBlocks, 256>>>(W2);
    k_aggpost<<<rowBlocks, 256>>>(out, 1);
}